// round 17
// baseline (speedup 1.0000x reference)
#include <cuda_runtime.h>
#include <cuda_fp16.h>
#include <cstdint>

// ---------------------------------------------------------------------------
// W4A16 grouped-quant linear: Y[M,N] = X[M,K] @ dequant(Wpacked)[K,N]
//  M=8192, K=4096, N=11008, group=128
//  Harness: x/scales/zeros float32, weight_packed int32, out float32;
//  compute_103 virtual target (no tcgen05) -> legacy mma.sync HMMA path.
//  K0: x f32 -> fp16 g_X
//  K1: REPACK int4 -> g_Bq: u32[kt][n][c] holds the 8 nibbles thread (c,n)
//      needs for its mma B-fragments of k-tile kt (k = kt*32 + P(c,i),
//      P = {2c,2c+1,2c+8,2c+9,2c+16,2c+17,2c+24,2c+25}).
//  K2: 128x128x32 GEMM (R14 skeleton: 4 warps 64x64, 4-stage cp.async,
//      2 CTAs/SM, wait->sync->loads->frags->mma) with IN-KERNEL B dequant:
//      B stage = 2KB of packed int4; dequant via 0x6400-magic (exact q),
//      then (q - z) * s in fp16x2 — bit-identical to the reference math.
//  Rules learned: cp_wait->sync->read (R11); loads >=2 iters ahead (R9);
//  BK=64 regresses (R9,R13); prepass fusion regresses (R12); R14 mainloop
//  order is a local optimum — do not reorder (R15,R16).
// ---------------------------------------------------------------------------

namespace {
constexpr int Mdim = 8192;
constexpr int Kdim = 4096;
constexpr int Ndim = 11008;
constexpr int GRP  = 128;

constexpr int BM = 128, BN = 128, BK = 32;
constexpr int STAGES = 4;
constexpr int ASTRIDE = BK + 8;           // 40 halves per A row
constexpr int TM = Mdim / BM;             // 64
constexpr int TN = Ndim / BN;             // 86
constexpr int KT = Kdim / BK;             // 128
constexpr int GROUP_M = 16;

constexpr int A_STAGE_BYTES = BM * ASTRIDE * 2;   // 10240
constexpr int B_STAGE_BYTES = BN * 4 * 4;         // 2048 (128 n x 4 u32)
constexpr int OFF_B  = STAGES * A_STAGE_BYTES;    // 40960
constexpr int OFF_SZ = OFF_B + STAGES * B_STAGE_BYTES; // 49152
constexpr int SMEM_BYTES = OFF_SZ + 32 * 128 * 4; // + sz table 16KB = 65536
}

// Static device scratch (no cudaMalloc allowed).
__device__ __align__(16) __half   g_X [(size_t)Mdim * Kdim];          // 64 MB
__device__ __align__(16) uint32_t g_Bq[(size_t)KT * Ndim * 4];        // 22.5 MB

// ---------------------------------------------------------------------------
// PTX helpers
// ---------------------------------------------------------------------------
__device__ __forceinline__ uint32_t smem_u32(const void* p) {
    return (uint32_t)__cvta_generic_to_shared(p);
}
__device__ __forceinline__ void cp_async16(uint32_t s, const void* g) {
    asm volatile("cp.async.cg.shared.global [%0], [%1], 16;\n" :: "r"(s), "l"(g));
}
__device__ __forceinline__ void cp_commit() {
    asm volatile("cp.async.commit_group;\n");
}
template <int N>
__device__ __forceinline__ void cp_wait() {
    asm volatile("cp.async.wait_group %0;\n" :: "n"(N));
}
__device__ __forceinline__ void ldsm_x4(uint32_t addr, uint32_t& r0, uint32_t& r1,
                                        uint32_t& r2, uint32_t& r3) {
    asm volatile("ldmatrix.sync.aligned.m8n8.x4.shared.b16 {%0,%1,%2,%3}, [%4];\n"
                 : "=r"(r0), "=r"(r1), "=r"(r2), "=r"(r3) : "r"(addr));
}
__device__ __forceinline__ uint32_t lds_b32(uint32_t addr) {
    uint32_t r;
    asm volatile("ld.shared.b32 %0, [%1];\n" : "=r"(r) : "r"(addr));
    return r;
}
__device__ __forceinline__ void mma16816(float& c0, float& c1, float& c2, float& c3,
                                         uint32_t a0, uint32_t a1, uint32_t a2, uint32_t a3,
                                         uint32_t b0, uint32_t b1) {
    asm volatile("mma.sync.aligned.m16n8k16.row.col.f32.f16.f16.f32 "
                 "{%0,%1,%2,%3}, {%4,%5,%6,%7}, {%8,%9}, {%0,%1,%2,%3};\n"
                 : "+f"(c0), "+f"(c1), "+f"(c2), "+f"(c3)
                 : "r"(a0), "r"(a1), "r"(a2), "r"(a3), "r"(b0), "r"(b1));
}
// (t1 & 0xF) | (t2 & 0xF0000) | 0x64006400  -> half2 {1024+q_lo, 1024+q_hi}
__device__ __forceinline__ uint32_t frag_pair(uint32_t t1, uint32_t t2) {
    uint32_t r;
    asm("lop3.b32 %0, %1, 0x0000000F, 0x64006400, 0xEA;\n" : "=r"(r) : "r"(t1));
    asm("lop3.b32 %0, %1, 0x000F0000, %0, 0xEA;\n" : "+r"(r) : "r"(t2));
    return r;
}
// ((p - 1024) - z) * s in fp16x2; (1024+q)-1024 is exact, rest matches ref.
__device__ __forceinline__ uint32_t dq(uint32_t p, uint32_t z2, uint32_t s2) {
    uint32_t r;
    asm("sub.rn.f16x2 %0, %1, %2;\n" : "=r"(r) : "r"(p), "r"(0x64006400u));
    asm("sub.rn.f16x2 %0, %0, %1;\n" : "+r"(r) : "r"(z2));
    asm("mul.rn.f16x2 %0, %0, %1;\n" : "+r"(r) : "r"(s2));
    return r;
}
__device__ __forceinline__ uint32_t dup_lo16(uint32_t v) {
    uint32_t r; asm("prmt.b32 %0, %1, %1, 0x1010;\n" : "=r"(r) : "r"(v)); return r;
}
__device__ __forceinline__ uint32_t dup_hi16(uint32_t v) {
    uint32_t r; asm("prmt.b32 %0, %1, %1, 0x3232;\n" : "=r"(r) : "r"(v)); return r;
}

// ---------------------------------------------------------------------------
// Kernel 0: x float32 -> fp16 (lossless)
// ---------------------------------------------------------------------------
__global__ void convert_x_kernel(const float* __restrict__ xf) {
    size_t i = ((size_t)blockIdx.x * blockDim.x + threadIdx.x) * 4;
    if (i >= (size_t)Mdim * Kdim) return;
    float4 v = *(const float4*)(xf + i);
    __align__(8) __half h[4];
    h[0] = __float2half_rn(v.x); h[1] = __float2half_rn(v.y);
    h[2] = __float2half_rn(v.z); h[3] = __float2half_rn(v.w);
    *(uint2*)(g_X + i) = *(uint2*)h;
}

// ---------------------------------------------------------------------------
// Kernel 1: repack int4 nibbles into fragment-ready u32s.
//  g_Bq[((kt*Ndim)+n)*4 + c] : nibble i (bits 4i..4i+3) = q(kt*32 + P(c,i), n)
//  q(k,n) = low nibble of wp[k][n] for k<2048, high nibble of wp[k-2048][n].
//  For a fixed kt all 32 k's share one nibble type (kt<64 -> low, else high).
// ---------------------------------------------------------------------------
__global__ void repack_kernel(const int* __restrict__ wp) {
    int kt = blockIdx.x / (Ndim / 256);     // 0..127
    int nb = blockIdx.x % (Ndim / 256);     // 0..42
    int n  = nb * 256 + threadIdx.x;
    int shift = (kt < 64) ? 0 : 4;
    int row0  = (kt & 63) * 32;
    const int* col = wp + (size_t)row0 * Ndim + n;

    uint32_t q[32];
#pragma unroll
    for (int j = 0; j < 32; j++)
        q[j] = ((uint32_t)col[(size_t)j * Ndim] >> shift) & 0xF;

    uint32_t out[4];
#pragma unroll
    for (int c = 0; c < 4; c++) {
        out[c] =  q[2*c]            | (q[2*c + 1]  << 4)
               | (q[2*c + 8]  << 8) | (q[2*c + 9]  << 12)
               | (q[2*c + 16] << 16)| (q[2*c + 17] << 20)
               | (q[2*c + 24] << 24)| (q[2*c + 25] << 28);
    }
    *(uint4*)(g_Bq + ((size_t)kt * Ndim + n) * 4) =
        make_uint4(out[0], out[1], out[2], out[3]);
}

// ---------------------------------------------------------------------------
// Kernel 2: fp16 GEMM with fused B dequant. CTA 128x128x32, 4 warps (64x64),
// 4-stage cp.async, single barrier/iter, 2 CTAs/SM. R14 skeleton.
// ---------------------------------------------------------------------------
__global__ void __launch_bounds__(128, 2) w4a16_gemm(const float* __restrict__ sc,
                                                     const float* __restrict__ zr,
                                                     float* __restrict__ Y) {
    extern __shared__ char smem[];
    const uint32_t sbase   = smem_u32(smem);
    const uint32_t b_base  = sbase + OFF_B;
    const uint32_t sz_base = sbase + OFF_SZ;

    const int tid  = threadIdx.x;
    const int lane = tid & 31;
    const int warp = tid >> 5;
    const int wm   = (warp >> 1) * 64;   // 0 / 64
    const int wn   = (warp & 1) * 64;    // 0 / 64

    // L2-friendly rasterization
    int pid = blockIdx.x;
    int per_group = GROUP_M * TN;
    int group = pid / per_group;
    int rem = pid - group * per_group;
    int pm = group * GROUP_M + (rem % GROUP_M);
    int pn = rem / GROUP_M;
    const int m0 = pm * BM;
    const int n0 = pn * BN;

    float acc[4][8][4];
#pragma unroll
    for (int i = 0; i < 4; i++)
#pragma unroll
        for (int j = 0; j < 8; j++)
#pragma unroll
            for (int k = 0; k < 4; k++) acc[i][j][k] = 0.f;

    auto load_tile = [&](int st, int kt) {
        const __half* gA0 = g_X + (size_t)m0 * Kdim + (size_t)kt * BK;
        uint32_t sa = sbase + st * A_STAGE_BYTES;
#pragma unroll
        for (int i = 0; i < 4; i++) {          // A: 512 16B chunks, 128 threads
            int c = tid + i * 128;
            int ar = c >> 2, acl = (c & 3) << 3;
            cp_async16(sa + (ar * ASTRIDE + acl) * 2, gA0 + (size_t)ar * Kdim + acl);
        }
        // B: 2KB packed int4, fully coalesced, 16B per thread
        cp_async16(b_base + st * B_STAGE_BYTES + tid * 16,
                   g_Bq + ((size_t)kt * Ndim + n0 + tid) * 4);
    };

    // ---- prologue: pipeline + scale/zero table ----
#pragma unroll
    for (int s = 0; s < STAGES - 1; s++) { load_tile(s, s); cp_commit(); }

    // sz table: half2(s, z) per (group, n_local): 32 x 128 entries
#pragma unroll
    for (int j = 0; j < 32; j++) {
        int g = j;                       // thread tid covers n_local = tid
        float s = sc[(size_t)g * Ndim + n0 + tid];
        float z = zr[(size_t)g * Ndim + n0 + tid];
        __half2 h = __halves2half2(__float2half_rn(s), __float2half_rn(z));
        *(__half2*)(smem + OFF_SZ + (g * 128 + tid) * 4) = h;
    }

    uint32_t a[2][4][4];   // A fragments, [ks][mf][reg]
    uint32_t braw[8];      // packed B u32 per nf
    uint32_t szc[8];       // half2(s,z) per nf

    for (int kt = 0; kt < KT; kt++) {
        // Per-thread drain FIRST (tile kt retired <=> pending <= 2), THEN the
        // barrier publishes all threads' copies (R11 lesson).
        cp_wait<2>();
        __syncthreads();

        // gmem loads for tile kt+3 (buffer (kt-1)%4, retired by the sync above)
        int lt = kt + STAGES - 1;
        if (lt < KT) load_tile(lt % STAGES, lt);
        cp_commit();

        int st = kt % STAGES;
        uint32_t sa_st = sbase + st * A_STAGE_BYTES;
        uint32_t sb_st = b_base + st * B_STAGE_BYTES;

        // scale/zero regs, refreshed once per quant group (4 iterations)
        if ((kt & 3) == 0) {
            int g = kt >> 2;
#pragma unroll
            for (int nf = 0; nf < 8; nf++)
                szc[nf] = lds_b32(sz_base + ((g << 7) + wn + nf * 8 + (lane >> 2)) * 4);
        }

        // packed B words (conflict-free: 32 consecutive u32 per warp access)
#pragma unroll
        for (int nf = 0; nf < 8; nf++)
            braw[nf] = lds_b32(sb_st + (wn + nf * 8 + (lane >> 2)) * 16 + (lane & 3) * 4);

        // A fragments (both k16 halves)
#pragma unroll
        for (int ks = 0; ks < 2; ks++)
#pragma unroll
            for (int mf = 0; mf < 4; mf++) {
                uint32_t addr = sa_st +
                    ((wm + mf * 16 + (lane & 15)) * ASTRIDE + ks * 16 + (lane >> 4) * 8) * 2;
                ldsm_x4(addr, a[ks][mf][0], a[ks][mf][1], a[ks][mf][2], a[ks][mf][3]);
            }

        // compute: dequant B per (ks, nf), then 4 mma down the m-fragments
#pragma unroll
        for (int ks = 0; ks < 2; ks++) {
#pragma unroll
            for (int nf = 0; nf < 8; nf++) {
                uint32_t v  = braw[nf];
                uint32_t s2 = dup_lo16(szc[nf]);
                uint32_t z2 = dup_hi16(szc[nf]);
                uint32_t t1a = (ks == 0) ? v         : (v >> 16);
                uint32_t t2a = (ks == 0) ? (v << 12) : (v >> 4);
                uint32_t t1b = (ks == 0) ? (v >> 8)  : (v >> 24);
                uint32_t t2b = (ks == 0) ? (v << 4)  : (v >> 12);
                uint32_t b0 = dq(frag_pair(t1a, t2a), z2, s2);  // k = 2c,2c+1 (+16ks)
                uint32_t b1 = dq(frag_pair(t1b, t2b), z2, s2);  // k = 2c+8,2c+9 (+16ks)
#pragma unroll
                for (int mf = 0; mf < 4; mf++)
                    mma16816(acc[mf][nf][0], acc[mf][nf][1], acc[mf][nf][2], acc[mf][nf][3],
                             a[ks][mf][0], a[ks][mf][1], a[ks][mf][2], a[ks][mf][3],
                             b0, b1);
            }
        }
    }

    // Epilogue: f32 accum -> fp16 round -> f32 store.
#pragma unroll
    for (int mf = 0; mf < 4; mf++) {
        int row = m0 + wm + mf * 16 + (lane >> 2);
#pragma unroll
        for (int nf = 0; nf < 8; nf++) {
            int col = n0 + wn + nf * 8 + (lane & 3) * 2;
            float v0 = __half2float(__float2half_rn(acc[mf][nf][0]));
            float v1 = __half2float(__float2half_rn(acc[mf][nf][1]));
            float v2 = __half2float(__float2half_rn(acc[mf][nf][2]));
            float v3 = __half2float(__float2half_rn(acc[mf][nf][3]));
            *(float2*)(Y + (size_t)row * Ndim + col)       = make_float2(v0, v1);
            *(float2*)(Y + (size_t)(row + 8) * Ndim + col) = make_float2(v2, v3);
        }
    }
}

// ---------------------------------------------------------------------------
// Launch. Inputs bound BY ELEMENT COUNT:
//   x: 33,554,432 f32 | weight_packed: 22,544,384 i32 | scales/zeros: 352,256 f32
// Output: float32 [M,N].
// ---------------------------------------------------------------------------
extern "C" void kernel_launch(void* const* d_in, const int* in_sizes, int n_in,
                              void* d_out, int out_size) {
    const float* x  = nullptr;
    const int*   wp = nullptr;
    const float* sc = nullptr;
    const float* zr = nullptr;
    for (int i = 0; i < n_in; i++) {
        long sz = in_sizes[i];
        if (sz == (long)Mdim * Kdim)            x  = (const float*)d_in[i];
        else if (sz == (long)(Kdim / 2) * Ndim) wp = (const int*)d_in[i];
        else if (sz == (long)(Kdim / GRP) * Ndim) {
            if (!sc) sc = (const float*)d_in[i];
            else     zr = (const float*)d_in[i];
        }
    }
    float* y = (float*)d_out;

    {
        size_t quads = (size_t)Mdim * Kdim / 4;
        convert_x_kernel<<<(int)((quads + 255) / 256), 256>>>(x);
    }
    repack_kernel<<<KT * (Ndim / 256), 256>>>(wp);

    cudaFuncSetAttribute(w4a16_gemm, cudaFuncAttributeMaxDynamicSharedMemorySize, SMEM_BYTES);
    w4a16_gemm<<<TM * TN, 128, SMEM_BYTES>>>(sc, zr, y);
}